// round 7
// baseline (speedup 1.0000x reference)
#include <cuda_runtime.h>
#include <cuda_bf16.h>

// ---------------------------------------------------------------------------
// RandomSpatialDeformation: svf upsample -> scaling&squaring (7) -> fused
// (80->160 upsample composed analytically into the final warp) -> warp of x.
// Flow field stored as float4 (z,y,x,0): every trilinear tap is 1x LDG.128.
// The fine flow u_e is NEVER materialized: sampling resize2x(v) at a real
// point is a separable 3-tap-per-axis weighted sum over coarse v (exact).
// ---------------------------------------------------------------------------

#define BATCH 2
#define SV    10
#define CDIM  80
#define FDIM  160

#define C2 (CDIM * CDIM)
#define C3 (CDIM * CDIM * CDIM)          // 512000
#define F2 (FDIM * FDIM)
#define F3 (FDIM * FDIM * FDIM)          // 4096000

#define BC3 (BATCH * C3)                 // 1024000
#define BF3 (BATCH * F3)                 // 8192000

__device__ float4 g_v4a[BC3];            // 16.4 MB
__device__ float4 g_v4b[BC3];            // 16.4 MB

__device__ __forceinline__ float flerp(float a, float b, float t) {
    return fmaf(t, b - a, a);
}
__device__ __forceinline__ float4 flerp4(float4 a, float4 b, float t) {
    return make_float4(fmaf(t, b.x - a.x, a.x), fmaf(t, b.y - a.y, a.y),
                       fmaf(t, b.z - a.z, a.z), fmaf(t, b.w - a.w, a.w));
}
__device__ __forceinline__ float4 fmadd4(float4 acc, float4 v, float w) {
    return make_float4(fmaf(w, v.x, acc.x), fmaf(w, v.y, acc.y),
                       fmaf(w, v.z, acc.z), fmaf(w, v.w, acc.w));
}
__device__ __forceinline__ float4 fscale4(float4 v, float w) {
    return make_float4(v.x * w, v.y * w, v.z * w, v.w * w);
}

// Trilinear sample of a float4 volume, D^3 spatial, clamped.
template <int D>
__device__ __forceinline__ float4 trisample4(const float4* __restrict__ vol,
                                             float z, float y, float x) {
    const float mx = (float)(D - 1);
    z = fminf(fmaxf(z, 0.0f), mx);
    y = fminf(fmaxf(y, 0.0f), mx);
    x = fminf(fmaxf(x, 0.0f), mx);
    float fz = floorf(z), fy = floorf(y), fx = floorf(x);
    int iz = (int)fz, iy = (int)fy, ix = (int)fx;
    float wz = z - fz, wy = y - fy, wx = x - fx;
    int iz1 = min(iz + 1, D - 1);
    int iy1 = min(iy + 1, D - 1);
    int ix1 = min(ix + 1, D - 1);

    const float4* p00 = vol + iz * (D * D) + iy * D;
    const float4* p01 = vol + iz * (D * D) + iy1 * D;
    const float4* p10 = vol + iz1 * (D * D) + iy * D;
    const float4* p11 = vol + iz1 * (D * D) + iy1 * D;

    float4 a0 = flerp4(p00[ix], p00[ix1], wx);
    float4 a1 = flerp4(p01[ix], p01[ix1], wx);
    float4 a2 = flerp4(p10[ix], p10[ix1], wx);
    float4 a3 = flerp4(p11[ix], p11[ix1], wx);
    return flerp4(flerp4(a0, a1, wy), flerp4(a2, a3, wy), wz);
}

// Scalar trilinear sample (for the image x), D^3 spatial, clamped.
template <int D>
__device__ __forceinline__ float trisample1(const float* __restrict__ vol,
                                            float z, float y, float x) {
    const float mx = (float)(D - 1);
    z = fminf(fmaxf(z, 0.0f), mx);
    y = fminf(fmaxf(y, 0.0f), mx);
    x = fminf(fmaxf(x, 0.0f), mx);
    float fz = floorf(z), fy = floorf(y), fx = floorf(x);
    int iz = (int)fz, iy = (int)fy, ix = (int)fx;
    float wz = z - fz, wy = y - fy, wx = x - fx;
    int iz1 = min(iz + 1, D - 1);
    int iy1 = min(iy + 1, D - 1);
    int ix1 = min(ix + 1, D - 1);

    const float* p00 = vol + iz * (D * D) + iy * D;
    const float* p01 = vol + iz * (D * D) + iy1 * D;
    const float* p10 = vol + iz1 * (D * D) + iy * D;
    const float* p11 = vol + iz1 * (D * D) + iy1 * D;

    float a0 = flerp(p00[ix], p00[ix1], wx);
    float a1 = flerp(p01[ix], p01[ix1], wx);
    float a2 = flerp(p10[ix], p10[ix1], wx);
    float a3 = flerp(p11[ix], p11[ix1], wx);
    return flerp(flerp(a0, a1, wy), flerp(a2, a3, wy), wz);
}

// ---- fine-lattice -> coarse decomposition for the 2x upsample ----
// u_e[k] (integer fine point) = w0*v[m] + w1*v[min(m+1,79)], exact parity form.
__device__ __forceinline__ void fine2coarse(int k, int& m, float& w0, float& w1) {
    if (k <= 0)     { m = 0;            w0 = 1.0f;  w1 = 0.0f;  }
    else if (k & 1) { m = k >> 1;       w0 = 0.75f; w1 = 0.25f; }
    else            { m = (k >> 1) - 1; w0 = 0.25f; w1 = 0.75f; }
}

// Per-axis composite weights for sampling resize2x(v) at real fine coord t:
// lerp_f over fine neighbors k0,k1 of their coarse 2-tap forms -> 3 taps at
// coarse base m0 (support m0..m0+2, index-clamped at 79 by the caller).
__device__ __forceinline__ void axis_weights(float t, int& m0,
                                             float& W0, float& W1, float& W2) {
    t = fminf(fmaxf(t, 0.0f), (float)(FDIM - 1));
    float ff = floorf(t);
    int k0 = (int)ff;
    float f = t - ff;
    int k1 = min(k0 + 1, FDIM - 1);
    int ma, mb;
    float a0, a1, b0, b1;
    fine2coarse(k0, ma, a0, a1);
    fine2coarse(k1, mb, b0, b1);
    float fi = 1.0f - f;
    if (mb == ma) {
        W0 = fi * a0 + f * b0;
        W1 = fi * a1 + f * b1;
        W2 = 0.0f;
    } else {  // mb == ma + 1
        W0 = fi * a0;
        W1 = fi * a1 + f * b0;
        W2 = f * b1;
    }
    m0 = ma;
}

// K1: resize svf [B,10,10,10,3] (AoS) -> g_v4a [B,80^3] float4, * 2^-7.
__global__ void __launch_bounds__(256) k_resize_svf(const float* __restrict__ svf) {
    int idx = blockIdx.x * 256 + threadIdx.x;
    if (idx >= BC3) return;
    int x = idx % CDIM;
    int y = (idx / CDIM) % CDIM;
    int z = (idx / C2) % CDIM;
    int b = idx / C3;

    float cz = (float)z * 0.125f - 0.4375f;
    float cy = (float)y * 0.125f - 0.4375f;
    float cx = (float)x * 0.125f - 0.4375f;
    const float mx = (float)(SV - 1);
    cz = fminf(fmaxf(cz, 0.0f), mx);
    cy = fminf(fmaxf(cy, 0.0f), mx);
    cx = fminf(fmaxf(cx, 0.0f), mx);
    float fz = floorf(cz), fy = floorf(cy), fx = floorf(cx);
    int iz = (int)fz, iy = (int)fy, ix = (int)fx;
    float wz = cz - fz, wy = cy - fy, wx = cx - fx;
    int iz1 = min(iz + 1, SV - 1);
    int iy1 = min(iy + 1, SV - 1);
    int ix1 = min(ix + 1, SV - 1);

    int base = b * SV * SV * SV;
    int p000 = (base + iz * SV * SV + iy * SV + ix) * 3;
    int p001 = (base + iz * SV * SV + iy * SV + ix1) * 3;
    int p010 = (base + iz * SV * SV + iy1 * SV + ix) * 3;
    int p011 = (base + iz * SV * SV + iy1 * SV + ix1) * 3;
    int p100 = (base + iz1 * SV * SV + iy * SV + ix) * 3;
    int p101 = (base + iz1 * SV * SV + iy * SV + ix1) * 3;
    int p110 = (base + iz1 * SV * SV + iy1 * SV + ix) * 3;
    int p111 = (base + iz1 * SV * SV + iy1 * SV + ix1) * 3;

    float r[3];
#pragma unroll
    for (int c = 0; c < 3; c++) {
        float a0 = flerp(svf[p000 + c], svf[p001 + c], wx);
        float a1 = flerp(svf[p010 + c], svf[p011 + c], wx);
        float a2 = flerp(svf[p100 + c], svf[p101 + c], wx);
        float a3 = flerp(svf[p110 + c], svf[p111 + c], wx);
        float b0 = flerp(a0, a1, wy);
        float b1 = flerp(a2, a3, wy);
        r[c] = flerp(b0, b1, wz) * (1.0f / 128.0f);
    }
    g_v4a[b * C3 + z * C2 + y * CDIM + x] = make_float4(r[0], r[1], r[2], 0.0f);
}

// K2: squaring step dst = v + trilinear(v, p + v). DIR=0: a->b, 1: b->a.
// (R4 form: 1 output/thread — best measured variant.)
template <int DIR>
__global__ void __launch_bounds__(256) k_square() {
    const float4* __restrict__ src = DIR ? g_v4b : g_v4a;
    float4* __restrict__ dst = DIR ? g_v4a : g_v4b;
    int idx = blockIdx.x * 256 + threadIdx.x;
    if (idx >= BC3) return;
    int x = idx % CDIM;
    int y = (idx / CDIM) % CDIM;
    int z = (idx / C2) % CDIM;
    int b = idx / C3;

    int lin = b * C3 + z * C2 + y * CDIM + x;
    float4 v = src[lin];

    float4 s = trisample4<CDIM>(src + b * C3,
                                (float)z + v.x, (float)y + v.y, (float)x + v.z);

    dst[lin] = make_float4(v.x + s.x, v.y + s.y, v.z + s.z, 0.0f);
}

// K3: fused (upsample + affine + flow sample + image sample).
// u = sample(resize2x(v), aff_loc) computed directly from coarse v via
// separable 3-tap weights; then out = sample(x, aff_loc + u).
__global__ void __launch_bounds__(256) k_final(const float* __restrict__ xin,
                                               const float* __restrict__ aff,
                                               float* __restrict__ out) {
    int idx = blockIdx.x * 256 + threadIdx.x;
    if (idx >= BF3) return;
    int x = idx % FDIM;
    int y = (idx / FDIM) % FDIM;
    int z = (idx / F2) % FDIM;
    int b = idx / F3;

    const float* A = aff + b * 16;  // row-major 4x4
    float gz = (float)z - 79.5f;
    float gy = (float)y - 79.5f;
    float gx = (float)x - 79.5f;

    float lz = fmaf(A[0], gz, fmaf(A[1], gy, fmaf(A[2], gx, 79.5f + A[3])));
    float ly = fmaf(A[4], gz, fmaf(A[5], gy, fmaf(A[6], gx, 79.5f + A[7])));
    float lx = fmaf(A[8], gz, fmaf(A[9], gy, fmaf(A[10], gx, 79.5f + A[11])));

    int mz, my, mx;
    float Wz0, Wz1, Wz2, Wy0, Wy1, Wy2, Wx0, Wx1, Wx2;
    axis_weights(lz, mz, Wz0, Wz1, Wz2);
    axis_weights(ly, my, Wy0, Wy1, Wy2);
    axis_weights(lx, mx, Wx0, Wx1, Wx2);

    const float4* __restrict__ vb = g_v4b + b * C3;
    int zo0 = mz * C2;
    int zo1 = min(mz + 1, CDIM - 1) * C2;
    int zo2 = min(mz + 2, CDIM - 1) * C2;
    int yo0 = my * CDIM;
    int yo1 = min(my + 1, CDIM - 1) * CDIM;
    int yo2 = min(my + 2, CDIM - 1) * CDIM;
    int x0 = mx;
    int x1 = min(mx + 1, CDIM - 1);
    int x2 = min(mx + 2, CDIM - 1);

    int zoff[3] = { zo0, zo1, zo2 };
    int yoff[3] = { yo0, yo1, yo2 };
    float wzv[3] = { Wz0, Wz1, Wz2 };
    float wyv[3] = { Wy0, Wy1, Wy2 };

    float4 u = make_float4(0.f, 0.f, 0.f, 0.f);
#pragma unroll
    for (int i = 0; i < 3; i++) {
        float4 plane = make_float4(0.f, 0.f, 0.f, 0.f);
#pragma unroll
        for (int j = 0; j < 3; j++) {
            const float4* row = vb + zoff[i] + yoff[j];
            float4 r = fscale4(row[x0], Wx0);
            r = fmadd4(r, row[x1], Wx1);
            r = fmadd4(r, row[x2], Wx2);
            plane = fmadd4(plane, r, wyv[j]);
        }
        u = fmadd4(u, plane, wzv[i]);
    }

    float s = trisample1<FDIM>(xin + b * F3, lz + u.x, ly + u.y, lx + u.z);
    out[b * F3 + z * F2 + y * FDIM + x] = s;
}

extern "C" void kernel_launch(void* const* d_in, const int* in_sizes, int n_in,
                              void* d_out, int out_size) {
    const float* x = nullptr;
    const float* aff = nullptr;
    const float* svf = nullptr;
    for (int i = 0; i < n_in; i++) {
        if (in_sizes[i] == BATCH * 16) {
            aff = (const float*)d_in[i];
        } else if (in_sizes[i] == BATCH * SV * SV * SV * 3) {
            svf = (const float*)d_in[i];
        } else {
            x = (const float*)d_in[i];
        }
    }

    const int gC = (BC3 + 255) / 256;
    const int gF = (BF3 + 255) / 256;

    k_resize_svf<<<gC, 256>>>(svf);
    // 7 steps: ends (DIR=0 last) with result in g_v4b
    k_square<0><<<gC, 256>>>();
    k_square<1><<<gC, 256>>>();
    k_square<0><<<gC, 256>>>();
    k_square<1><<<gC, 256>>>();
    k_square<0><<<gC, 256>>>();
    k_square<1><<<gC, 256>>>();
    k_square<0><<<gC, 256>>>();
    k_final<<<gF, 256>>>(x, aff, (float*)d_out);
}